// round 14
// baseline (speedup 1.0000x reference)
#include <cuda_runtime.h>
#include <cuda_fp16.h>
#include <cstdint>
#include <math.h>

#define S_LEN 2048
#define HID   5120
#define NH    40
#define HD    128
#define QKV_N (3*HID)   // 15360

// ---- fp16 mma GEMM tiling: KT=64, padded rows (16B-period pad) ----
#define MT 128
#define NT 128
#define KT 64
#define BSTR 72                         // halves per smem row (64 data + 8 pad)
#define TILE_BYTES (128*BSTR*2)         // 18432 per operand tile
#define STAGE_BYTES (2*TILE_BYTES)      // A + B = 36864
#define STAGES 3
#define GEMM_SMEM (STAGES*STAGE_BYTES)  // 110592 (x2 CTA = 221184)

// ---- flash-attention (fp16 tensor, BQ=128, triple-buffered K/V) ----
#define BQ 128
#define BKV 64
#define AQS 136                          // halves stride for 128-wide rows
#define KV_TILE (BKV*AQS*2)              // 17408
#define Q_TILE  (BQ*AQS*2)               // 34816
#define KVBUF   (3*KV_TILE)              // Kh,Kl,Vh = 52224
#define KV_STAGES 3
#define FSMEM   (2*Q_TILE + KV_STAGES*KVBUF)   // 226304

// Scratch (allocation-free rule: __device__ globals)
__device__ __half g_qkvh[(size_t)S_LEN * QKV_N];       // QKV hi fp16
__device__ __half g_qkvl[(size_t)S_LEN * QKV_N];       // QKV lo fp16 (Q,K only)
__device__ __half g_h16[(size_t)S_LEN * HID];          // hidden fp16
__device__ __half g_wp16[(size_t)QKV_N * HID];         // Wpack fp16 (plain)
__device__ __half g_wo16[(size_t)HID * HID];           // Wo fp16
__device__ __half g_attno16[(size_t)S_LEN * HID];      // attention out fp16

// ============================================================================
// PTX helpers
// ============================================================================
__device__ __forceinline__ uint32_t smem_u32(const void* p) {
    uint32_t a;
    asm("{ .reg .u64 t; cvta.to.shared.u64 t, %1; cvt.u32.u64 %0, t; }"
        : "=r"(a) : "l"(p));
    return a;
}

__device__ __forceinline__ void ldsm4(uint32_t* r, uint32_t a) {
    asm volatile("ldmatrix.sync.aligned.m8n8.x4.shared.b16 {%0,%1,%2,%3}, [%4];"
                 : "=r"(r[0]), "=r"(r[1]), "=r"(r[2]), "=r"(r[3]) : "r"(a));
}
__device__ __forceinline__ void ldsm4t(uint32_t* r, uint32_t a) {
    asm volatile("ldmatrix.sync.aligned.m8n8.x4.trans.shared.b16 {%0,%1,%2,%3}, [%4];"
                 : "=r"(r[0]), "=r"(r[1]), "=r"(r[2]), "=r"(r[3]) : "r"(a));
}

__device__ __forceinline__ void mma16(float* c, const uint32_t* a,
                                      uint32_t b0, uint32_t b1) {
    asm volatile(
        "mma.sync.aligned.m16n8k16.row.col.f32.f16.f16.f32 "
        "{%0,%1,%2,%3}, {%4,%5,%6,%7}, {%8,%9}, {%0,%1,%2,%3};"
        : "+f"(c[0]), "+f"(c[1]), "+f"(c[2]), "+f"(c[3])
        : "r"(a[0]), "r"(a[1]), "r"(a[2]), "r"(a[3]), "r"(b0), "r"(b1));
}

__device__ __forceinline__ uint32_t packh2(float a, float b) {
    __half2 h = __floats2half2_rn(a, b);
    return *reinterpret_cast<uint32_t*>(&h);
}

__device__ __forceinline__ uint2 cvt4(const float4 v) {
    uint2 r; r.x = packh2(v.x, v.y); r.y = packh2(v.z, v.w); return r;
}

__device__ __forceinline__ void cpa16(uint32_t dst, const void* src) {
    asm volatile("cp.async.cg.shared.global [%0], [%1], 16;"
                 :: "r"(dst), "l"(src) : "memory");
}
__device__ __forceinline__ void cp_commit() {
    asm volatile("cp.async.commit_group;" ::: "memory");
}
template<int N> __device__ __forceinline__ void cp_wait() {
    asm volatile("cp.async.wait_group %0;" :: "n"(N) : "memory");
}

// ============================================================================
// Pre-conversion: fused plain conversions (hidden, Wpack full, Wo)
// ============================================================================
__global__ void cvt_fused3_kernel(const float4* __restrict__ a, uint2* __restrict__ ao, int na,
                                  const float4* __restrict__ b, uint2* __restrict__ bo, int nb,
                                  const float4* __restrict__ c, uint2* __restrict__ co, int nc) {
    const int tot = na + nb + nc;
    for (int i = blockIdx.x * blockDim.x + threadIdx.x; i < tot;
         i += gridDim.x * blockDim.x) {
        if (i < na) ao[i] = cvt4(a[i]);
        else if (i < na + nb) bo[i - na] = cvt4(b[i - na]);
        else co[i - na - nb] = cvt4(c[i - na - nb]);
    }
}

// ============================================================================
// fp16 tensor GEMM (TN), plain B, KT=64, 3-stage cp.async pipeline, 2 CTAs/SM.
// (byte-identical to R13)
// SPLITOUT: write hi/lo fp16 split of the fp32 accumulator (lo for n0<2*HID).
// ============================================================================
template<bool SPLITOUT>
__global__ __launch_bounds__(256, 2)
void gemm16p(const __half* __restrict__ A, const __half* __restrict__ Bh,
             float* __restrict__ Cf,
             __half* __restrict__ Chi, __half* __restrict__ Clo,
             int M, int N, int K) {
    extern __shared__ __align__(16) char sm[];
    const uint32_t sb = smem_u32(sm);

    const int t   = threadIdx.x;
    const int wid = t >> 5;
    const int ln  = t & 31;
    const int m0  = blockIdx.x * MT;
    const int n0  = blockIdx.y * NT;
    const int wm  = (wid >> 1) * 32;
    const int wn  = (wid & 1) * 64;

    const int r0 = t >> 3;
    const int sg = t & 7;
    const __half* Ag = A  + (size_t)(m0 + r0) * K + sg * 8;
    const __half* Bg = Bh + (size_t)(n0 + r0) * K + sg * 8;
    uint32_t dA[4];
#pragma unroll
    for (int i = 0; i < 4; i++)
        dA[i] = (uint32_t)(r0 + 32 * i) * (BSTR * 2) + sg * 16;

    const uint32_t aoff = ((uint32_t)(wm + (ln & 15)) * BSTR + 8u * (ln >> 4)) * 2;
    const uint32_t boff = TILE_BYTES +
        ((uint32_t)(wn + (ln & 7) + 8 * (ln >> 4)) * BSTR + 8u * ((ln >> 3) & 1)) * 2;

    float acc[2][8][4];
#pragma unroll
    for (int mi = 0; mi < 2; mi++)
#pragma unroll
        for (int nf = 0; nf < 8; nf++)
#pragma unroll
            for (int r = 0; r < 4; r++) acc[mi][nf][r] = 0.0f;

    const int NKT = K / KT;   // 80

    auto issue = [&](int st, int kt) {
        const uint32_t base = sb + (uint32_t)st * STAGE_BYTES;
        const size_t ko = (size_t)kt * KT;
#pragma unroll
        for (int i = 0; i < 4; i++) {
            cpa16(base + dA[i], Ag + (size_t)(32 * i) * K + ko);
            cpa16(base + TILE_BYTES + dA[i], Bg + (size_t)(32 * i) * K + ko);
        }
    };

#pragma unroll
    for (int s = 0; s < STAGES - 1; s++) { issue(s, s); cp_commit(); }

#pragma unroll 1
    for (int kt = 0; kt < NKT; kt++) {
        cp_wait<STAGES - 2>();
        __syncthreads();

        const uint32_t so = sb + (uint32_t)(kt % STAGES) * STAGE_BYTES;
#pragma unroll
        for (int ks = 0; ks < 4; ks++) {
            const uint32_t ko = ks * 32;   // 16 halves
            uint32_t af[2][4];
            ldsm4(af[0], so + aoff + ko);
            ldsm4(af[1], so + aoff + 16 * BSTR * 2 + ko);
            uint32_t bh[4][4];
#pragma unroll
            for (int p = 0; p < 4; p++)
                ldsm4(bh[p], so + boff + p * (16 * BSTR * 2) + ko);
#pragma unroll
            for (int mi = 0; mi < 2; mi++)
#pragma unroll
                for (int nf = 0; nf < 8; nf++)
                    mma16(acc[mi][nf], af[mi],
                          bh[nf >> 1][(nf & 1) * 2], bh[nf >> 1][(nf & 1) * 2 + 1]);
        }

        const int nk = kt + STAGES - 1;
        if (nk < NKT) issue(nk % STAGES, nk);
        cp_commit();
    }

    // epilogue
    const bool writeLo = SPLITOUT && (n0 < 2 * HID);   // Q,K get hi/lo outputs
#pragma unroll
    for (int mi = 0; mi < 2; mi++) {
        const int r = m0 + wm + mi * 16 + (ln >> 2);
#pragma unroll
        for (int nf = 0; nf < 8; nf++) {
            const int cc = n0 + wn + nf * 8 + (ln & 3) * 2;
            if (SPLITOUT) {
#pragma unroll
                for (int hh = 0; hh < 2; hh++) {
                    const float v0 = acc[mi][nf][2 * hh], v1 = acc[mi][nf][2 * hh + 1];
                    const __half h0 = __float2half_rn(v0), h1 = __float2half_rn(v1);
                    const size_t off = (size_t)(r + 8 * hh) * N + cc;
                    *(uint32_t*)(Chi + off) = packh2(v0, v1);
                    if (writeLo)
                        *(uint32_t*)(Clo + off) =
                            packh2(v0 - __half2float(h0), v1 - __half2float(h1));
                }
            } else {
                *(float2*)(Cf + (size_t)r * N + cc) =
                    make_float2(acc[mi][nf][0], acc[mi][nf][1]);
                *(float2*)(Cf + (size_t)(r + 8) * N + cc) =
                    make_float2(acc[mi][nf][2], acc[mi][nf][3]);
            }
        }
    }
}

// ============================================================================
// Flash attention, fp16 tensor, causal. BQ=128, 256 thr, 3-stage K/V.
// SOFTWARE-PIPELINED: softmax+PV for block kb-1 overlap the S MMAs of block
// kb (softmax no longer depends on in-flight MMA results).
// S = QhKh + QhKl + QlKh; O += P*Vh. Grid (NH, S/BQ) with qb reversed.
// ============================================================================
__global__ __launch_bounds__(256, 1)
void flash16_kernel(const __half* __restrict__ qh, const __half* __restrict__ ql,
                    __half* __restrict__ out) {
    extern __shared__ __align__(16) char sm[];
    const uint32_t sb = smem_u32(sm);
    const uint32_t uQh = sb;
    const uint32_t uQl = sb + Q_TILE;
    const uint32_t uBuf0 = sb + 2 * Q_TILE;

    const int head = blockIdx.x;
    const int qb   = (int)gridDim.y - 1 - (int)blockIdx.y;   // heavy first
    const int q0   = qb * BQ;
    const int t    = threadIdx.x;
    const int w    = t >> 5;
    const int ln   = t & 31;
    const int m0w  = w * 16;
    const float scale = 0.08838834764831845f;   // 1/sqrt(128)

    const int lr  = t >> 2;            // 0..63
    const int lc  = (t & 3) * 4;       // chunk base 0,4,8,12

    auto issueKV = [&](int kb) {
        const uint32_t base = uBuf0 + (uint32_t)(kb % KV_STAGES) * KVBUF;
        const size_t gk = (size_t)(kb * BKV + lr) * QKV_N + HID + head * HD;
        const size_t gv = gk + HID;
        const uint32_t ro = (uint32_t)lr * (AQS * 2);
#pragma unroll
        for (int i = 0; i < 4; i++) {
            const int c = lc + i;
            cpa16(base + ro + c * 16, qh + gk + c * 8);                    // Kh
            cpa16(base + KV_TILE + ro + c * 16, ql + gk + c * 8);          // Kl
            cpa16(base + 2 * KV_TILE + ro + c * 16, qh + gv + c * 8);      // Vh
        }
    };

    // ---- prologue: Q + KV0 as one group, KV1 as second ----
#pragma unroll
    for (int pass = 0; pass < 2; pass++) {
        const int r = pass * 64 + lr;
        const size_t go = (size_t)(q0 + r) * QKV_N + head * HD;
        const uint32_t ro = (uint32_t)r * (AQS * 2);
#pragma unroll
        for (int i = 0; i < 4; i++) {
            const int c = lc + i;
            cpa16(uQh + ro + c * 16, qh + go + c * 8);
            cpa16(uQl + ro + c * 16, ql + go + c * 8);
        }
    }
    issueKV(0);
    cp_commit();          // group: Q + KV0
    issueKV(1);
    cp_commit();          // group: KV1

    const int nkb = 2 * (qb + 1);

    cp_wait<1>();         // Q + KV0 ready
    __syncthreads();

    // ---- hoist Qh fragments to registers (Ql reloaded per block; reg budget) ----
    const uint32_t aQ = ((uint32_t)(m0w + (ln & 15)) * AQS + 8u * (ln >> 4)) * 2;
    uint32_t qhf[8][4];
#pragma unroll
    for (int ks = 0; ks < 8; ks++)
        ldsm4(qhf[ks], uQh + aQ + ks * 32);

    float m_i[2] = {-1e30f, -1e30f};
    float l_i[2] = {0.0f, 0.0f};
    float o[16][4];
#pragma unroll
    for (int d = 0; d < 16; d++)
#pragma unroll
        for (int r = 0; r < 4; r++) o[d][r] = 0.0f;

    const uint32_t bK = ((uint32_t)((ln & 7) + 8 * (ln >> 4)) * AQS + 8u * ((ln >> 3) & 1)) * 2;
    const uint32_t bV = ((uint32_t)((ln & 7) + 8 * ((ln >> 3) & 1)) * AQS + 8u * (ln >> 4)) * 2;

    const int r1g = q0 + m0w + (ln >> 2);
    const int r2g = r1g + 8;
    const int lastS = q0 + m0w + 15;   // warp active while k0 <= lastS

    float s_prev[8][4];
    bool  have_prev = false;

#pragma unroll 1
    for (int kb = 0; kb <= nkb; kb++) {
        const int k0 = kb * BKV;
        const bool doS = (kb < nkb) && (k0 <= lastS);

        // ---- S MMAs for block kb (raw scores into s_new) ----
        float s_new[8][4];
        if (doS) {
            const uint32_t cKh = uBuf0 + (uint32_t)(kb % KV_STAGES) * KVBUF;
            const uint32_t cKl = cKh + KV_TILE;
#pragma unroll
            for (int nf = 0; nf < 8; nf++)
#pragma unroll
                for (int r = 0; r < 4; r++) s_new[nf][r] = 0.0f;
#pragma unroll
            for (int ks = 0; ks < 8; ks++) {
                const uint32_t ko = ks * 32;
                uint32_t qlf[4];
                ldsm4(qlf, uQl + aQ + ko);
                uint32_t kh[4][4], kl[4][4];
#pragma unroll
                for (int p = 0; p < 4; p++) {
                    ldsm4(kh[p], cKh + bK + p * (16 * AQS * 2) + ko);
                    ldsm4(kl[p], cKl + bK + p * (16 * AQS * 2) + ko);
                }
#pragma unroll
                for (int nf = 0; nf < 8; nf++) {
                    const uint32_t h0 = kh[nf >> 1][(nf & 1) * 2];
                    const uint32_t h1 = kh[nf >> 1][(nf & 1) * 2 + 1];
                    const uint32_t l0 = kl[nf >> 1][(nf & 1) * 2];
                    const uint32_t l1 = kl[nf >> 1][(nf & 1) * 2 + 1];
                    mma16(s_new[nf], qhf[ks], h0, h1);
                    mma16(s_new[nf], qhf[ks], l0, l1);
                    mma16(s_new[nf], qlf,     h0, h1);
                }
            }
        }

        // ---- softmax + PV for block kb-1 (independent of in-flight MMAs) ----
        if (have_prev) {
            const int k0p = (kb - 1) * BKV;
            const bool needMask = (k0p + BKV - 1 > q0 + m0w);
            float mx1 = -1e30f, mx2 = -1e30f;
#pragma unroll
            for (int nf = 0; nf < 8; nf++) {
                float v0 = s_prev[nf][0] * scale, v1 = s_prev[nf][1] * scale;
                float v2 = s_prev[nf][2] * scale, v3 = s_prev[nf][3] * scale;
                if (needMask) {
                    const int cb = k0p + nf * 8 + 2 * (ln & 3);
                    if (cb     > r1g) v0 = -1e30f;
                    if (cb + 1 > r1g) v1 = -1e30f;
                    if (cb     > r2g) v2 = -1e30f;
                    if (cb + 1 > r2g) v3 = -1e30f;
                }
                s_prev[nf][0] = v0; s_prev[nf][1] = v1;
                s_prev[nf][2] = v2; s_prev[nf][3] = v3;
                mx1 = fmaxf(mx1, fmaxf(v0, v1));
                mx2 = fmaxf(mx2, fmaxf(v2, v3));
            }
            mx1 = fmaxf(mx1, __shfl_xor_sync(0xffffffffu, mx1, 1));
            mx1 = fmaxf(mx1, __shfl_xor_sync(0xffffffffu, mx1, 2));
            mx2 = fmaxf(mx2, __shfl_xor_sync(0xffffffffu, mx2, 1));
            mx2 = fmaxf(mx2, __shfl_xor_sync(0xffffffffu, mx2, 2));

            const float mn1 = fmaxf(m_i[0], mx1);
            const float mn2 = fmaxf(m_i[1], mx2);
            const float corr1 = __expf(m_i[0] - mn1);
            const float corr2 = __expf(m_i[1] - mn2);
            m_i[0] = mn1; m_i[1] = mn2;

            float rs1 = 0.0f, rs2 = 0.0f;
#pragma unroll
            for (int nf = 0; nf < 8; nf++) {
                float p0 = __expf(s_prev[nf][0] - mn1);
                float p1 = __expf(s_prev[nf][1] - mn1);
                float p2 = __expf(s_prev[nf][2] - mn2);
                float p3 = __expf(s_prev[nf][3] - mn2);
                rs1 += p0 + p1; rs2 += p2 + p3;
                s_prev[nf][0] = p0; s_prev[nf][1] = p1;
                s_prev[nf][2] = p2; s_prev[nf][3] = p3;
            }
            rs1 += __shfl_xor_sync(0xffffffffu, rs1, 1);
            rs1 += __shfl_xor_sync(0xffffffffu, rs1, 2);
            rs2 += __shfl_xor_sync(0xffffffffu, rs2, 1);
            rs2 += __shfl_xor_sync(0xffffffffu, rs2, 2);
            l_i[0] = l_i[0] * corr1 + rs1;
            l_i[1] = l_i[1] * corr2 + rs2;

#pragma unroll
            for (int d = 0; d < 16; d++) {
                o[d][0] *= corr1; o[d][1] *= corr1;
                o[d][2] *= corr2; o[d][3] *= corr2;
            }

            uint32_t pa[4][4];
#pragma unroll
            for (int tk = 0; tk < 4; tk++) {
                pa[tk][0] = packh2(s_prev[2 * tk][0],     s_prev[2 * tk][1]);
                pa[tk][1] = packh2(s_prev[2 * tk][2],     s_prev[2 * tk][3]);
                pa[tk][2] = packh2(s_prev[2 * tk + 1][0], s_prev[2 * tk + 1][1]);
                pa[tk][3] = packh2(s_prev[2 * tk + 1][2], s_prev[2 * tk + 1][3]);
            }

            const uint32_t cVh = uBuf0 + (uint32_t)((kb - 1) % KV_STAGES) * KVBUF
                               + 2 * KV_TILE;
#pragma unroll
            for (int tk = 0; tk < 4; tk++) {
                const uint32_t rowo = (uint32_t)(16 * tk) * AQS * 2;
#pragma unroll
                for (int p = 0; p < 8; p++) {
                    uint32_t vh[4];
                    ldsm4t(vh, cVh + rowo + bV + (uint32_t)p * 32);
                    mma16(o[2 * p],     pa[tk], vh[0], vh[1]);
                    mma16(o[2 * p + 1], pa[tk], vh[2], vh[3]);
                }
            }
        }

        if (kb >= nkb) break;   // final deferred PV done

        // all warps finished reading K(kb) and V(kb-1) -> stage (kb+2)%3 reusable
        __syncthreads();
        if (kb + 2 < nkb) issueKV(kb + 2);
        cp_commit();
        if (kb + 1 < nkb) {
            cp_wait<1>();      // K/V(kb+1) landed
            __syncthreads();
        }

        // rotate raw scores
        if (doS) {
#pragma unroll
            for (int nf = 0; nf < 8; nf++)
#pragma unroll
                for (int r = 0; r < 4; r++) s_prev[nf][r] = s_new[nf][r];
        }
        have_prev = doS;
    }

    // ---- epilogue: fp16 output ----
    const float inv1 = 1.0f / l_i[0];
    const float inv2 = 1.0f / l_i[1];
#pragma unroll
    for (int d = 0; d < 16; d++) {
        const int cc = head * HD + d * 8 + 2 * (ln & 3);
        *(__half2*)(out + (size_t)r1g * HID + cc) =
            __floats2half2_rn(o[d][0] * inv1, o[d][1] * inv1);
        *(__half2*)(out + (size_t)r2g * HID + cc) =
            __floats2half2_rn(o[d][2] * inv2, o[d][3] * inv2);
    }
}

// ============================================================================
// Launch
// ============================================================================
extern "C" void kernel_launch(void* const* d_in, const int* in_sizes, int n_in,
                              void* d_out, int out_size) {
    const float* hidden = (const float*)d_in[0];
    const float* wpack  = (const float*)d_in[1];
    const float* wo     = (const float*)d_in[2];
    float* out = (float*)d_out;

    __half *qkvh, *qkvl, *h16, *wp16, *wo16, *at16;
    cudaGetSymbolAddress((void**)&qkvh, g_qkvh);
    cudaGetSymbolAddress((void**)&qkvl, g_qkvl);
    cudaGetSymbolAddress((void**)&h16,  g_h16);
    cudaGetSymbolAddress((void**)&wp16, g_wp16);
    cudaGetSymbolAddress((void**)&wo16, g_wo16);
    cudaGetSymbolAddress((void**)&at16, g_attno16);

    cudaFuncSetAttribute((const void*)gemm16p<true>,
                         cudaFuncAttributeMaxDynamicSharedMemorySize, GEMM_SMEM);
    cudaFuncSetAttribute((const void*)gemm16p<false>,
                         cudaFuncAttributeMaxDynamicSharedMemorySize, GEMM_SMEM);
    cudaFuncSetAttribute((const void*)flash16_kernel,
                         cudaFuncAttributeMaxDynamicSharedMemorySize, FSMEM);

    // 0. pre-conversions: H, Wpack (full), Wo -> plain fp16
    cvt_fused3_kernel<<<8192, 256>>>(
        (const float4*)hidden, (uint2*)h16, (int)((size_t)S_LEN * HID / 4),
        (const float4*)wpack, (uint2*)wp16, (int)((size_t)QKV_N * HID / 4),
        (const float4*)wo, (uint2*)wo16, (int)((size_t)HID * HID / 4));

    // 1. QKV projection (plain fp16 B; split-out hi/lo for Q,K)
    dim3 g1(S_LEN / MT, QKV_N / NT);
    gemm16p<true><<<g1, 256, GEMM_SMEM>>>(
        h16, wp16, nullptr, qkvh, qkvl, S_LEN, QKV_N, HID);

    // 2. Causal flash attention (BQ=128, pipelined softmax/PV) -> fp16
    dim3 g2(NH, S_LEN / BQ);
    flash16_kernel<<<g2, 256, FSMEM>>>(qkvh, qkvl, at16);

    // 3. Output projection (plain fp16) -> fp32 out
    dim3 g3(S_LEN / MT, HID / NT);
    gemm16p<false><<<g3, 256, GEMM_SMEM>>>(
        at16, wo16, out, nullptr, nullptr, S_LEN, HID, HID);
}

// round 15
// speedup vs baseline: 1.0342x; 1.0342x over previous
#include <cuda_runtime.h>
#include <cuda_fp16.h>
#include <cstdint>
#include <math.h>

#define S_LEN 2048
#define HID   5120
#define NH    40
#define HD    128
#define QKV_N (3*HID)   // 15360

// ---- fp16 mma GEMM tiling: KT=64, padded rows (16B-period pad) ----
#define MT 128
#define NT 128
#define KT 64
#define BSTR 72                         // halves per smem row (64 data + 8 pad)
#define TILE_BYTES (128*BSTR*2)         // 18432 per operand tile
#define STAGE_BYTES (2*TILE_BYTES)      // A + B = 36864
#define STAGES 3
#define GEMM_SMEM (STAGES*STAGE_BYTES)  // 110592 (x2 CTA = 221184)

// ---- flash-attention (fp16 tensor, BQ=128, triple-buffered K/V) ----
#define BQ 128
#define BKV 64
#define AQS 136                          // halves stride for 128-wide rows
#define KV_TILE (BKV*AQS*2)              // 17408
#define Q_TILE  (BQ*AQS*2)               // 34816
#define KVBUF   (3*KV_TILE)              // Kh,Kl,Vh = 52224
#define KV_STAGES 3
#define FSMEM   (Q_TILE + KV_STAGES*KVBUF)   // 191488

// Scratch (allocation-free rule: __device__ globals)
__device__ __half g_qkvh[(size_t)S_LEN * QKV_N];       // QKV hi fp16
__device__ __half g_qkvl[(size_t)S_LEN * QKV_N];       // QKV lo fp16 (K only used)
__device__ __half g_h16[(size_t)S_LEN * HID];          // hidden fp16
__device__ __half g_wp16[(size_t)QKV_N * HID];         // Wpack fp16 (plain)
__device__ __half g_wo16[(size_t)HID * HID];           // Wo fp16
__device__ __half g_attno16[(size_t)S_LEN * HID];      // attention out fp16

// ============================================================================
// PTX helpers
// ============================================================================
__device__ __forceinline__ uint32_t smem_u32(const void* p) {
    uint32_t a;
    asm("{ .reg .u64 t; cvta.to.shared.u64 t, %1; cvt.u32.u64 %0, t; }"
        : "=r"(a) : "l"(p));
    return a;
}

__device__ __forceinline__ void ldsm4(uint32_t* r, uint32_t a) {
    asm volatile("ldmatrix.sync.aligned.m8n8.x4.shared.b16 {%0,%1,%2,%3}, [%4];"
                 : "=r"(r[0]), "=r"(r[1]), "=r"(r[2]), "=r"(r[3]) : "r"(a));
}
__device__ __forceinline__ void ldsm4t(uint32_t* r, uint32_t a) {
    asm volatile("ldmatrix.sync.aligned.m8n8.x4.trans.shared.b16 {%0,%1,%2,%3}, [%4];"
                 : "=r"(r[0]), "=r"(r[1]), "=r"(r[2]), "=r"(r[3]) : "r"(a));
}

__device__ __forceinline__ void mma16(float* c, const uint32_t* a,
                                      uint32_t b0, uint32_t b1) {
    asm volatile(
        "mma.sync.aligned.m16n8k16.row.col.f32.f16.f16.f32 "
        "{%0,%1,%2,%3}, {%4,%5,%6,%7}, {%8,%9}, {%0,%1,%2,%3};"
        : "+f"(c[0]), "+f"(c[1]), "+f"(c[2]), "+f"(c[3])
        : "r"(a[0]), "r"(a[1]), "r"(a[2]), "r"(a[3]), "r"(b0), "r"(b1));
}

__device__ __forceinline__ uint32_t packh2(float a, float b) {
    __half2 h = __floats2half2_rn(a, b);
    return *reinterpret_cast<uint32_t*>(&h);
}

__device__ __forceinline__ uint2 cvt4(const float4 v) {
    uint2 r; r.x = packh2(v.x, v.y); r.y = packh2(v.z, v.w); return r;
}

__device__ __forceinline__ void cpa16(uint32_t dst, const void* src) {
    asm volatile("cp.async.cg.shared.global [%0], [%1], 16;"
                 :: "r"(dst), "l"(src) : "memory");
}
__device__ __forceinline__ void cp_commit() {
    asm volatile("cp.async.commit_group;" ::: "memory");
}
template<int N> __device__ __forceinline__ void cp_wait() {
    asm volatile("cp.async.wait_group %0;" :: "n"(N) : "memory");
}

// ============================================================================
// Pre-conversion: fused plain conversions (hidden, Wpack full, Wo)
// ============================================================================
__global__ void cvt_fused3_kernel(const float4* __restrict__ a, uint2* __restrict__ ao, int na,
                                  const float4* __restrict__ b, uint2* __restrict__ bo, int nb,
                                  const float4* __restrict__ c, uint2* __restrict__ co, int nc) {
    const int tot = na + nb + nc;
    for (int i = blockIdx.x * blockDim.x + threadIdx.x; i < tot;
         i += gridDim.x * blockDim.x) {
        if (i < na) ao[i] = cvt4(a[i]);
        else if (i < na + nb) bo[i - na] = cvt4(b[i - na]);
        else co[i - na - nb] = cvt4(c[i - na - nb]);
    }
}

// ============================================================================
// fp16 tensor GEMM (TN), plain B, KT=64, 3-stage cp.async pipeline, 2 CTAs/SM.
// (R13 loop structure unchanged)
// SPLITOUT: hi fp16 split everywhere; lo only for K tiles (HID <= n0 < 2*HID).
// ============================================================================
template<bool SPLITOUT>
__global__ __launch_bounds__(256, 2)
void gemm16p(const __half* __restrict__ A, const __half* __restrict__ Bh,
             float* __restrict__ Cf,
             __half* __restrict__ Chi, __half* __restrict__ Clo,
             int M, int N, int K) {
    extern __shared__ __align__(16) char sm[];
    const uint32_t sb = smem_u32(sm);

    const int t   = threadIdx.x;
    const int wid = t >> 5;
    const int ln  = t & 31;
    const int m0  = blockIdx.x * MT;
    const int n0  = blockIdx.y * NT;
    const int wm  = (wid >> 1) * 32;
    const int wn  = (wid & 1) * 64;

    const int r0 = t >> 3;
    const int sg = t & 7;
    const __half* Ag = A  + (size_t)(m0 + r0) * K + sg * 8;
    const __half* Bg = Bh + (size_t)(n0 + r0) * K + sg * 8;
    uint32_t dA[4];
#pragma unroll
    for (int i = 0; i < 4; i++)
        dA[i] = (uint32_t)(r0 + 32 * i) * (BSTR * 2) + sg * 16;

    const uint32_t aoff = ((uint32_t)(wm + (ln & 15)) * BSTR + 8u * (ln >> 4)) * 2;
    const uint32_t boff = TILE_BYTES +
        ((uint32_t)(wn + (ln & 7) + 8 * (ln >> 4)) * BSTR + 8u * ((ln >> 3) & 1)) * 2;

    float acc[2][8][4];
#pragma unroll
    for (int mi = 0; mi < 2; mi++)
#pragma unroll
        for (int nf = 0; nf < 8; nf++)
#pragma unroll
            for (int r = 0; r < 4; r++) acc[mi][nf][r] = 0.0f;

    const int NKT = K / KT;   // 80

    auto issue = [&](int st, int kt) {
        const uint32_t base = sb + (uint32_t)st * STAGE_BYTES;
        const size_t ko = (size_t)kt * KT;
#pragma unroll
        for (int i = 0; i < 4; i++) {
            cpa16(base + dA[i], Ag + (size_t)(32 * i) * K + ko);
            cpa16(base + TILE_BYTES + dA[i], Bg + (size_t)(32 * i) * K + ko);
        }
    };

#pragma unroll
    for (int s = 0; s < STAGES - 1; s++) { issue(s, s); cp_commit(); }

#pragma unroll 1
    for (int kt = 0; kt < NKT; kt++) {
        cp_wait<STAGES - 2>();
        __syncthreads();

        const uint32_t so = sb + (uint32_t)(kt % STAGES) * STAGE_BYTES;
#pragma unroll
        for (int ks = 0; ks < 4; ks++) {
            const uint32_t ko = ks * 32;   // 16 halves
            uint32_t af[2][4];
            ldsm4(af[0], so + aoff + ko);
            ldsm4(af[1], so + aoff + 16 * BSTR * 2 + ko);
            uint32_t bh[4][4];
#pragma unroll
            for (int p = 0; p < 4; p++)
                ldsm4(bh[p], so + boff + p * (16 * BSTR * 2) + ko);
#pragma unroll
            for (int mi = 0; mi < 2; mi++)
#pragma unroll
                for (int nf = 0; nf < 8; nf++)
                    mma16(acc[mi][nf], af[mi],
                          bh[nf >> 1][(nf & 1) * 2], bh[nf >> 1][(nf & 1) * 2 + 1]);
        }

        const int nk = kt + STAGES - 1;
        if (nk < NKT) issue(nk % STAGES, nk);
        cp_commit();
    }

    // epilogue
    const bool writeLo = SPLITOUT && (n0 >= HID) && (n0 < 2 * HID);   // K tiles only
#pragma unroll
    for (int mi = 0; mi < 2; mi++) {
        const int r = m0 + wm + mi * 16 + (ln >> 2);
#pragma unroll
        for (int nf = 0; nf < 8; nf++) {
            const int cc = n0 + wn + nf * 8 + (ln & 3) * 2;
            if (SPLITOUT) {
#pragma unroll
                for (int hh = 0; hh < 2; hh++) {
                    const float v0 = acc[mi][nf][2 * hh], v1 = acc[mi][nf][2 * hh + 1];
                    const __half h0 = __float2half_rn(v0), h1 = __float2half_rn(v1);
                    const size_t off = (size_t)(r + 8 * hh) * N + cc;
                    *(uint32_t*)(Chi + off) = packh2(v0, v1);
                    if (writeLo)
                        *(uint32_t*)(Clo + off) =
                            packh2(v0 - __half2float(h0), v1 - __half2float(h1));
                }
            } else {
                *(float2*)(Cf + (size_t)r * N + cc) =
                    make_float2(acc[mi][nf][0], acc[mi][nf][1]);
                *(float2*)(Cf + (size_t)(r + 8) * N + cc) =
                    make_float2(acc[mi][nf][2], acc[mi][nf][3]);
            }
        }
    }
}

// ============================================================================
// Flash attention (R13 structure), fp16 tensor, causal. BQ=128, 256 thr,
// triple-buffered K/V via cp.async; one sync per KV block; Qh in registers.
// S = Qh*Kh + Qh*Kl (K compensated; Q plain). O += P*Vh.
// Grid (NH, S/BQ) with qb reversed.
// ============================================================================
__global__ __launch_bounds__(256, 1)
void flash16_kernel(const __half* __restrict__ qh, const __half* __restrict__ ql,
                    __half* __restrict__ out) {
    extern __shared__ __align__(16) char sm[];
    const uint32_t sb = smem_u32(sm);
    const uint32_t uQh = sb;
    const uint32_t uBuf0 = sb + Q_TILE;

    const int head = blockIdx.x;
    const int qb   = (int)gridDim.y - 1 - (int)blockIdx.y;   // heavy first
    const int q0   = qb * BQ;
    const int t    = threadIdx.x;
    const int w    = t >> 5;
    const int ln   = t & 31;
    const int m0w  = w * 16;
    const float scale = 0.08838834764831845f;   // 1/sqrt(128)

    const int lr  = t >> 2;            // 0..63
    const int lc  = (t & 3) * 4;       // chunk base 0,4,8,12

    auto issueKV = [&](int kb) {
        const uint32_t base = uBuf0 + (uint32_t)(kb % KV_STAGES) * KVBUF;
        const size_t gk = (size_t)(kb * BKV + lr) * QKV_N + HID + head * HD;
        const size_t gv = gk + HID;
        const uint32_t ro = (uint32_t)lr * (AQS * 2);
#pragma unroll
        for (int i = 0; i < 4; i++) {
            const int c = lc + i;
            cpa16(base + ro + c * 16, qh + gk + c * 8);                    // Kh
            cpa16(base + KV_TILE + ro + c * 16, ql + gk + c * 8);          // Kl
            cpa16(base + 2 * KV_TILE + ro + c * 16, qh + gv + c * 8);      // Vh
        }
    };

    // ---- prologue: Qh + KV0 as one group, KV1 as second ----
#pragma unroll
    for (int pass = 0; pass < 2; pass++) {
        const int r = pass * 64 + lr;
        const size_t go = (size_t)(q0 + r) * QKV_N + head * HD;
        const uint32_t ro = (uint32_t)r * (AQS * 2);
#pragma unroll
        for (int i = 0; i < 4; i++) {
            const int c = lc + i;
            cpa16(uQh + ro + c * 16, qh + go + c * 8);
        }
    }
    issueKV(0);
    cp_commit();          // group: Qh + KV0
    issueKV(1);
    cp_commit();          // group: KV1

    const int nkb = 2 * (qb + 1);

    cp_wait<1>();         // Qh + KV0 ready
    __syncthreads();

    // ---- hoist Qh fragments to registers ----
    const uint32_t aQ = ((uint32_t)(m0w + (ln & 15)) * AQS + 8u * (ln >> 4)) * 2;
    uint32_t qhf[8][4];
#pragma unroll
    for (int ks = 0; ks < 8; ks++)
        ldsm4(qhf[ks], uQh + aQ + ks * 32);

    float m_i[2] = {-1e30f, -1e30f};
    float l_i[2] = {0.0f, 0.0f};
    float o[16][4];
#pragma unroll
    for (int d = 0; d < 16; d++)
#pragma unroll
        for (int r = 0; r < 4; r++) o[d][r] = 0.0f;

    const uint32_t bK = ((uint32_t)((ln & 7) + 8 * (ln >> 4)) * AQS + 8u * ((ln >> 3) & 1)) * 2;
    const uint32_t bV = ((uint32_t)((ln & 7) + 8 * ((ln >> 3) & 1)) * AQS + 8u * (ln >> 4)) * 2;

    const int r1g = q0 + m0w + (ln >> 2);
    const int r2g = r1g + 8;

#pragma unroll 1
    for (int kb = 0; kb < nkb; kb++) {
        const int k0 = kb * BKV;

        if (kb + 2 < nkb) issueKV(kb + 2);
        cp_commit();

        if (k0 <= q0 + m0w + 15) {
            const uint32_t cKh = uBuf0 + (uint32_t)(kb % KV_STAGES) * KVBUF;
            const uint32_t cKl = cKh + KV_TILE;
            const uint32_t cVh = cKh + 2 * KV_TILE;

            float s[8][4];
#pragma unroll
            for (int nf = 0; nf < 8; nf++)
#pragma unroll
                for (int r = 0; r < 4; r++) s[nf][r] = 0.0f;

#pragma unroll
            for (int ks = 0; ks < 8; ks++) {
                const uint32_t ko = ks * 32;
                uint32_t kh[4][4], kl[4][4];
#pragma unroll
                for (int p = 0; p < 4; p++) {
                    ldsm4(kh[p], cKh + bK + p * (16 * AQS * 2) + ko);
                    ldsm4(kl[p], cKl + bK + p * (16 * AQS * 2) + ko);
                }
#pragma unroll
                for (int nf = 0; nf < 8; nf++) {
                    const uint32_t h0 = kh[nf >> 1][(nf & 1) * 2];
                    const uint32_t h1 = kh[nf >> 1][(nf & 1) * 2 + 1];
                    const uint32_t l0 = kl[nf >> 1][(nf & 1) * 2];
                    const uint32_t l1 = kl[nf >> 1][(nf & 1) * 2 + 1];
                    mma16(s[nf], qhf[ks], h0, h1);
                    mma16(s[nf], qhf[ks], l0, l1);
                }
            }

            const bool needMask = (k0 + BKV - 1 > q0 + m0w);
            float mx1 = -1e30f, mx2 = -1e30f;
#pragma unroll
            for (int nf = 0; nf < 8; nf++) {
                float v0 = s[nf][0] * scale, v1 = s[nf][1] * scale;
                float v2 = s[nf][2] * scale, v3 = s[nf][3] * scale;
                if (needMask) {
                    const int cb = k0 + nf * 8 + 2 * (ln & 3);
                    if (cb     > r1g) v0 = -1e30f;
                    if (cb + 1 > r1g) v1 = -1e30f;
                    if (cb     > r2g) v2 = -1e30f;
                    if (cb + 1 > r2g) v3 = -1e30f;
                }
                s[nf][0] = v0; s[nf][1] = v1; s[nf][2] = v2; s[nf][3] = v3;
                mx1 = fmaxf(mx1, fmaxf(v0, v1));
                mx2 = fmaxf(mx2, fmaxf(v2, v3));
            }
            mx1 = fmaxf(mx1, __shfl_xor_sync(0xffffffffu, mx1, 1));
            mx1 = fmaxf(mx1, __shfl_xor_sync(0xffffffffu, mx1, 2));
            mx2 = fmaxf(mx2, __shfl_xor_sync(0xffffffffu, mx2, 1));
            mx2 = fmaxf(mx2, __shfl_xor_sync(0xffffffffu, mx2, 2));

            const float mn1 = fmaxf(m_i[0], mx1);
            const float mn2 = fmaxf(m_i[1], mx2);
            const float corr1 = __expf(m_i[0] - mn1);
            const float corr2 = __expf(m_i[1] - mn2);
            m_i[0] = mn1; m_i[1] = mn2;

            float rs1 = 0.0f, rs2 = 0.0f;
#pragma unroll
            for (int nf = 0; nf < 8; nf++) {
                float p0 = __expf(s[nf][0] - mn1);
                float p1 = __expf(s[nf][1] - mn1);
                float p2 = __expf(s[nf][2] - mn2);
                float p3 = __expf(s[nf][3] - mn2);
                rs1 += p0 + p1; rs2 += p2 + p3;
                s[nf][0] = p0; s[nf][1] = p1; s[nf][2] = p2; s[nf][3] = p3;
            }
            rs1 += __shfl_xor_sync(0xffffffffu, rs1, 1);
            rs1 += __shfl_xor_sync(0xffffffffu, rs1, 2);
            rs2 += __shfl_xor_sync(0xffffffffu, rs2, 1);
            rs2 += __shfl_xor_sync(0xffffffffu, rs2, 2);
            l_i[0] = l_i[0] * corr1 + rs1;
            l_i[1] = l_i[1] * corr2 + rs2;

#pragma unroll
            for (int d = 0; d < 16; d++) {
                o[d][0] *= corr1; o[d][1] *= corr1;
                o[d][2] *= corr2; o[d][3] *= corr2;
            }

            uint32_t pa[4][4];
#pragma unroll
            for (int tk = 0; tk < 4; tk++) {
                pa[tk][0] = packh2(s[2 * tk][0],     s[2 * tk][1]);
                pa[tk][1] = packh2(s[2 * tk][2],     s[2 * tk][3]);
                pa[tk][2] = packh2(s[2 * tk + 1][0], s[2 * tk + 1][1]);
                pa[tk][3] = packh2(s[2 * tk + 1][2], s[2 * tk + 1][3]);
            }

#pragma unroll
            for (int tk = 0; tk < 4; tk++) {
                const uint32_t rowo = (uint32_t)(16 * tk) * AQS * 2;
#pragma unroll
                for (int p = 0; p < 8; p++) {
                    uint32_t vh[4];
                    ldsm4t(vh, cVh + rowo + bV + (uint32_t)p * 32);
                    mma16(o[2 * p],     pa[tk], vh[0], vh[1]);
                    mma16(o[2 * p + 1], pa[tk], vh[2], vh[3]);
                }
            }
        }

        if (kb + 1 < nkb) {
            cp_wait<1>();      // next block's K/V landed
            __syncthreads();   // single barrier per iteration
        }
    }

    // ---- epilogue: fp16 output ----
    const float inv1 = 1.0f / l_i[0];
    const float inv2 = 1.0f / l_i[1];
#pragma unroll
    for (int d = 0; d < 16; d++) {
        const int cc = head * HD + d * 8 + 2 * (ln & 3);
        *(__half2*)(out + (size_t)r1g * HID + cc) =
            __floats2half2_rn(o[d][0] * inv1, o[d][1] * inv1);
        *(__half2*)(out + (size_t)r2g * HID + cc) =
            __floats2half2_rn(o[d][2] * inv2, o[d][3] * inv2);
    }
}

// ============================================================================
// Launch
// ============================================================================
extern "C" void kernel_launch(void* const* d_in, const int* in_sizes, int n_in,
                              void* d_out, int out_size) {
    const float* hidden = (const float*)d_in[0];
    const float* wpack  = (const float*)d_in[1];
    const float* wo     = (const float*)d_in[2];
    float* out = (float*)d_out;

    __half *qkvh, *qkvl, *h16, *wp16, *wo16, *at16;
    cudaGetSymbolAddress((void**)&qkvh, g_qkvh);
    cudaGetSymbolAddress((void**)&qkvl, g_qkvl);
    cudaGetSymbolAddress((void**)&h16,  g_h16);
    cudaGetSymbolAddress((void**)&wp16, g_wp16);
    cudaGetSymbolAddress((void**)&wo16, g_wo16);
    cudaGetSymbolAddress((void**)&at16, g_attno16);

    cudaFuncSetAttribute((const void*)gemm16p<true>,
                         cudaFuncAttributeMaxDynamicSharedMemorySize, GEMM_SMEM);
    cudaFuncSetAttribute((const void*)gemm16p<false>,
                         cudaFuncAttributeMaxDynamicSharedMemorySize, GEMM_SMEM);
    cudaFuncSetAttribute((const void*)flash16_kernel,
                         cudaFuncAttributeMaxDynamicSharedMemorySize, FSMEM);

    // 0. pre-conversions: H, Wpack (full), Wo -> plain fp16
    cvt_fused3_kernel<<<8192, 256>>>(
        (const float4*)hidden, (uint2*)h16, (int)((size_t)S_LEN * HID / 4),
        (const float4*)wpack, (uint2*)wp16, (int)((size_t)QKV_N * HID / 4),
        (const float4*)wo, (uint2*)wo16, (int)((size_t)HID * HID / 4));

    // 1. QKV projection (plain fp16 B; split-out hi everywhere, lo for K)
    dim3 g1(S_LEN / MT, QKV_N / NT);
    gemm16p<true><<<g1, 256, GEMM_SMEM>>>(
        h16, wp16, nullptr, qkvh, qkvl, S_LEN, QKV_N, HID);

    // 2. Causal flash attention (BQ=128, K-compensated only) -> fp16
    dim3 g2(NH, S_LEN / BQ);
    flash16_kernel<<<g2, 256, FSMEM>>>(qkvh, qkvl, at16);

    // 3. Output projection (plain fp16) -> fp32 out
    dim3 g3(S_LEN / MT, HID / NT);
    gemm16p<false><<<g3, 256, GEMM_SMEM>>>(
        at16, wo16, out, nullptr, nullptr, S_LEN, HID, HID);
}

// round 16
// speedup vs baseline: 1.0649x; 1.0297x over previous
#include <cuda_runtime.h>
#include <cuda_fp16.h>
#include <cstdint>
#include <math.h>

#define S_LEN 2048
#define HID   5120
#define NH    40
#define HD    128
#define QKV_N (3*HID)   // 15360

// ---- fp16 mma GEMM tiling: KT=64, padded rows (16B-period pad) ----
#define MT 128
#define NT 128
#define KT 64
#define BSTR 72                         // halves per smem row (64 data + 8 pad)
#define TILE_BYTES (128*BSTR*2)         // 18432 per operand tile
#define STAGE_BYTES (2*TILE_BYTES)      // A + B = 36864
#define STAGES 3
#define GEMM_SMEM (STAGES*STAGE_BYTES)  // 110592 (x2 CTA = 221184)

// ---- flash-attention (fp16 tensor, BQ=128, triple-buffered K/V) ----
#define BQ 128
#define BKV 64
#define AQS 136                          // halves stride for 128-wide rows
#define KV_TILE (BKV*AQS*2)              // 17408
#define Q_TILE  (BQ*AQS*2)               // 34816
#define KVBUF   (2*KV_TILE)              // Kh,Vh = 34816
#define KV_STAGES 3
#define FSMEM   (Q_TILE + KV_STAGES*KVBUF)   // 139264

// Scratch (allocation-free rule: __device__ globals)
__device__ __half g_qkvh[(size_t)S_LEN * QKV_N];       // QKV fp16
__device__ __half g_h16[(size_t)S_LEN * HID];          // hidden fp16
__device__ __half g_wp16[(size_t)QKV_N * HID];         // Wpack fp16
__device__ __half g_wo16[(size_t)HID * HID];           // Wo fp16
__device__ __half g_attno16[(size_t)S_LEN * HID];      // attention out fp16

// ============================================================================
// PTX helpers
// ============================================================================
__device__ __forceinline__ uint32_t smem_u32(const void* p) {
    uint32_t a;
    asm("{ .reg .u64 t; cvta.to.shared.u64 t, %1; cvt.u32.u64 %0, t; }"
        : "=r"(a) : "l"(p));
    return a;
}

__device__ __forceinline__ void ldsm4(uint32_t* r, uint32_t a) {
    asm volatile("ldmatrix.sync.aligned.m8n8.x4.shared.b16 {%0,%1,%2,%3}, [%4];"
                 : "=r"(r[0]), "=r"(r[1]), "=r"(r[2]), "=r"(r[3]) : "r"(a));
}
__device__ __forceinline__ void ldsm4t(uint32_t* r, uint32_t a) {
    asm volatile("ldmatrix.sync.aligned.m8n8.x4.trans.shared.b16 {%0,%1,%2,%3}, [%4];"
                 : "=r"(r[0]), "=r"(r[1]), "=r"(r[2]), "=r"(r[3]) : "r"(a));
}

__device__ __forceinline__ void mma16(float* c, const uint32_t* a,
                                      uint32_t b0, uint32_t b1) {
    asm volatile(
        "mma.sync.aligned.m16n8k16.row.col.f32.f16.f16.f32 "
        "{%0,%1,%2,%3}, {%4,%5,%6,%7}, {%8,%9}, {%0,%1,%2,%3};"
        : "+f"(c[0]), "+f"(c[1]), "+f"(c[2]), "+f"(c[3])
        : "r"(a[0]), "r"(a[1]), "r"(a[2]), "r"(a[3]), "r"(b0), "r"(b1));
}

__device__ __forceinline__ uint32_t packh2(float a, float b) {
    __half2 h = __floats2half2_rn(a, b);
    return *reinterpret_cast<uint32_t*>(&h);
}

__device__ __forceinline__ uint2 cvt4(const float4 v) {
    uint2 r; r.x = packh2(v.x, v.y); r.y = packh2(v.z, v.w); return r;
}

__device__ __forceinline__ void cpa16(uint32_t dst, const void* src) {
    asm volatile("cp.async.cg.shared.global [%0], [%1], 16;"
                 :: "r"(dst), "l"(src) : "memory");
}
__device__ __forceinline__ void cp_commit() {
    asm volatile("cp.async.commit_group;" ::: "memory");
}
template<int N> __device__ __forceinline__ void cp_wait() {
    asm volatile("cp.async.wait_group %0;" :: "n"(N) : "memory");
}

// ============================================================================
// Pre-conversion: fused plain conversions (hidden, Wpack full, Wo)
// ============================================================================
__global__ void cvt_fused3_kernel(const float4* __restrict__ a, uint2* __restrict__ ao, int na,
                                  const float4* __restrict__ b, uint2* __restrict__ bo, int nb,
                                  const float4* __restrict__ c, uint2* __restrict__ co, int nc) {
    const int tot = na + nb + nc;
    for (int i = blockIdx.x * blockDim.x + threadIdx.x; i < tot;
         i += gridDim.x * blockDim.x) {
        if (i < na) ao[i] = cvt4(a[i]);
        else if (i < na + nb) bo[i - na] = cvt4(b[i - na]);
        else co[i - na - nb] = cvt4(c[i - na - nb]);
    }
}

// ============================================================================
// fp16 tensor GEMM (TN), plain B, KT=64, 3-stage cp.async pipeline, 2 CTAs/SM.
// (R13 loop structure unchanged)
// HALFOUT: write fp16 output (QKV path); else fp32 (final output).
// ============================================================================
template<bool HALFOUT>
__global__ __launch_bounds__(256, 2)
void gemm16p(const __half* __restrict__ A, const __half* __restrict__ Bh,
             float* __restrict__ Cf, __half* __restrict__ Chi,
             int M, int N, int K) {
    extern __shared__ __align__(16) char sm[];
    const uint32_t sb = smem_u32(sm);

    const int t   = threadIdx.x;
    const int wid = t >> 5;
    const int ln  = t & 31;
    const int m0  = blockIdx.x * MT;
    const int n0  = blockIdx.y * NT;
    const int wm  = (wid >> 1) * 32;
    const int wn  = (wid & 1) * 64;

    const int r0 = t >> 3;
    const int sg = t & 7;
    const __half* Ag = A  + (size_t)(m0 + r0) * K + sg * 8;
    const __half* Bg = Bh + (size_t)(n0 + r0) * K + sg * 8;
    uint32_t dA[4];
#pragma unroll
    for (int i = 0; i < 4; i++)
        dA[i] = (uint32_t)(r0 + 32 * i) * (BSTR * 2) + sg * 16;

    const uint32_t aoff = ((uint32_t)(wm + (ln & 15)) * BSTR + 8u * (ln >> 4)) * 2;
    const uint32_t boff = TILE_BYTES +
        ((uint32_t)(wn + (ln & 7) + 8 * (ln >> 4)) * BSTR + 8u * ((ln >> 3) & 1)) * 2;

    float acc[2][8][4];
#pragma unroll
    for (int mi = 0; mi < 2; mi++)
#pragma unroll
        for (int nf = 0; nf < 8; nf++)
#pragma unroll
            for (int r = 0; r < 4; r++) acc[mi][nf][r] = 0.0f;

    const int NKT = K / KT;   // 80

    auto issue = [&](int st, int kt) {
        const uint32_t base = sb + (uint32_t)st * STAGE_BYTES;
        const size_t ko = (size_t)kt * KT;
#pragma unroll
        for (int i = 0; i < 4; i++) {
            cpa16(base + dA[i], Ag + (size_t)(32 * i) * K + ko);
            cpa16(base + TILE_BYTES + dA[i], Bg + (size_t)(32 * i) * K + ko);
        }
    };

#pragma unroll
    for (int s = 0; s < STAGES - 1; s++) { issue(s, s); cp_commit(); }

#pragma unroll 1
    for (int kt = 0; kt < NKT; kt++) {
        cp_wait<STAGES - 2>();
        __syncthreads();

        const uint32_t so = sb + (uint32_t)(kt % STAGES) * STAGE_BYTES;
#pragma unroll
        for (int ks = 0; ks < 4; ks++) {
            const uint32_t ko = ks * 32;   // 16 halves
            uint32_t af[2][4];
            ldsm4(af[0], so + aoff + ko);
            ldsm4(af[1], so + aoff + 16 * BSTR * 2 + ko);
            uint32_t bh[4][4];
#pragma unroll
            for (int p = 0; p < 4; p++)
                ldsm4(bh[p], so + boff + p * (16 * BSTR * 2) + ko);
#pragma unroll
            for (int mi = 0; mi < 2; mi++)
#pragma unroll
                for (int nf = 0; nf < 8; nf++)
                    mma16(acc[mi][nf], af[mi],
                          bh[nf >> 1][(nf & 1) * 2], bh[nf >> 1][(nf & 1) * 2 + 1]);
        }

        const int nk = kt + STAGES - 1;
        if (nk < NKT) issue(nk % STAGES, nk);
        cp_commit();
    }

    // epilogue
#pragma unroll
    for (int mi = 0; mi < 2; mi++) {
        const int r = m0 + wm + mi * 16 + (ln >> 2);
#pragma unroll
        for (int nf = 0; nf < 8; nf++) {
            const int cc = n0 + wn + nf * 8 + (ln & 3) * 2;
            if (HALFOUT) {
#pragma unroll
                for (int hh = 0; hh < 2; hh++) {
                    const size_t off = (size_t)(r + 8 * hh) * N + cc;
                    *(uint32_t*)(Chi + off) =
                        packh2(acc[mi][nf][2 * hh], acc[mi][nf][2 * hh + 1]);
                }
            } else {
                *(float2*)(Cf + (size_t)r * N + cc) =
                    make_float2(acc[mi][nf][0], acc[mi][nf][1]);
                *(float2*)(Cf + (size_t)(r + 8) * N + cc) =
                    make_float2(acc[mi][nf][2], acc[mi][nf][3]);
            }
        }
    }
}

// ============================================================================
// Flash attention (R13/R15 structure), fp16 tensor, causal. BQ=128, 256 thr,
// triple-buffered K/V (Kh,Vh only) via cp.async; one sync per KV block;
// Qh in registers. S = Qh*Kh (plain fp16). O += P*Vh.
// Grid (NH, S/BQ) with qb reversed.
// ============================================================================
__global__ __launch_bounds__(256, 1)
void flash16_kernel(const __half* __restrict__ qkv, __half* __restrict__ out) {
    extern __shared__ __align__(16) char sm[];
    const uint32_t sb = smem_u32(sm);
    const uint32_t uQh = sb;
    const uint32_t uBuf0 = sb + Q_TILE;

    const int head = blockIdx.x;
    const int qb   = (int)gridDim.y - 1 - (int)blockIdx.y;   // heavy first
    const int q0   = qb * BQ;
    const int t    = threadIdx.x;
    const int w    = t >> 5;
    const int ln   = t & 31;
    const int m0w  = w * 16;
    const float scale = 0.08838834764831845f;   // 1/sqrt(128)

    const int lr  = t >> 2;            // 0..63
    const int lc  = (t & 3) * 4;       // chunk base 0,4,8,12

    auto issueKV = [&](int kb) {
        const uint32_t base = uBuf0 + (uint32_t)(kb % KV_STAGES) * KVBUF;
        const size_t gk = (size_t)(kb * BKV + lr) * QKV_N + HID + head * HD;
        const size_t gv = gk + HID;
        const uint32_t ro = (uint32_t)lr * (AQS * 2);
#pragma unroll
        for (int i = 0; i < 4; i++) {
            const int c = lc + i;
            cpa16(base + ro + c * 16, qkv + gk + c * 8);                   // Kh
            cpa16(base + KV_TILE + ro + c * 16, qkv + gv + c * 8);         // Vh
        }
    };

    // ---- prologue: Qh + KV0 as one group, KV1 as second ----
#pragma unroll
    for (int pass = 0; pass < 2; pass++) {
        const int r = pass * 64 + lr;
        const size_t go = (size_t)(q0 + r) * QKV_N + head * HD;
        const uint32_t ro = (uint32_t)r * (AQS * 2);
#pragma unroll
        for (int i = 0; i < 4; i++) {
            const int c = lc + i;
            cpa16(uQh + ro + c * 16, qkv + go + c * 8);
        }
    }
    issueKV(0);
    cp_commit();          // group: Qh + KV0
    issueKV(1);
    cp_commit();          // group: KV1

    const int nkb = 2 * (qb + 1);

    cp_wait<1>();         // Qh + KV0 ready
    __syncthreads();

    // ---- hoist Qh fragments to registers ----
    const uint32_t aQ = ((uint32_t)(m0w + (ln & 15)) * AQS + 8u * (ln >> 4)) * 2;
    uint32_t qhf[8][4];
#pragma unroll
    for (int ks = 0; ks < 8; ks++)
        ldsm4(qhf[ks], uQh + aQ + ks * 32);

    float m_i[2] = {-1e30f, -1e30f};
    float l_i[2] = {0.0f, 0.0f};
    float o[16][4];
#pragma unroll
    for (int d = 0; d < 16; d++)
#pragma unroll
        for (int r = 0; r < 4; r++) o[d][r] = 0.0f;

    const uint32_t bK = ((uint32_t)((ln & 7) + 8 * (ln >> 4)) * AQS + 8u * ((ln >> 3) & 1)) * 2;
    const uint32_t bV = ((uint32_t)((ln & 7) + 8 * ((ln >> 3) & 1)) * AQS + 8u * (ln >> 4)) * 2;

    const int r1g = q0 + m0w + (ln >> 2);
    const int r2g = r1g + 8;

#pragma unroll 1
    for (int kb = 0; kb < nkb; kb++) {
        const int k0 = kb * BKV;

        if (kb + 2 < nkb) issueKV(kb + 2);
        cp_commit();

        if (k0 <= q0 + m0w + 15) {
            const uint32_t cKh = uBuf0 + (uint32_t)(kb % KV_STAGES) * KVBUF;
            const uint32_t cVh = cKh + KV_TILE;

            float s[8][4];
#pragma unroll
            for (int nf = 0; nf < 8; nf++)
#pragma unroll
                for (int r = 0; r < 4; r++) s[nf][r] = 0.0f;

#pragma unroll
            for (int ks = 0; ks < 8; ks++) {
                const uint32_t ko = ks * 32;
                uint32_t kh[4][4];
#pragma unroll
                for (int p = 0; p < 4; p++)
                    ldsm4(kh[p], cKh + bK + p * (16 * AQS * 2) + ko);
#pragma unroll
                for (int nf = 0; nf < 8; nf++)
                    mma16(s[nf], qhf[ks],
                          kh[nf >> 1][(nf & 1) * 2], kh[nf >> 1][(nf & 1) * 2 + 1]);
            }

            const bool needMask = (k0 + BKV - 1 > q0 + m0w);
            float mx1 = -1e30f, mx2 = -1e30f;
#pragma unroll
            for (int nf = 0; nf < 8; nf++) {
                float v0 = s[nf][0] * scale, v1 = s[nf][1] * scale;
                float v2 = s[nf][2] * scale, v3 = s[nf][3] * scale;
                if (needMask) {
                    const int cb = k0 + nf * 8 + 2 * (ln & 3);
                    if (cb     > r1g) v0 = -1e30f;
                    if (cb + 1 > r1g) v1 = -1e30f;
                    if (cb     > r2g) v2 = -1e30f;
                    if (cb + 1 > r2g) v3 = -1e30f;
                }
                s[nf][0] = v0; s[nf][1] = v1; s[nf][2] = v2; s[nf][3] = v3;
                mx1 = fmaxf(mx1, fmaxf(v0, v1));
                mx2 = fmaxf(mx2, fmaxf(v2, v3));
            }
            mx1 = fmaxf(mx1, __shfl_xor_sync(0xffffffffu, mx1, 1));
            mx1 = fmaxf(mx1, __shfl_xor_sync(0xffffffffu, mx1, 2));
            mx2 = fmaxf(mx2, __shfl_xor_sync(0xffffffffu, mx2, 1));
            mx2 = fmaxf(mx2, __shfl_xor_sync(0xffffffffu, mx2, 2));

            const float mn1 = fmaxf(m_i[0], mx1);
            const float mn2 = fmaxf(m_i[1], mx2);
            const float corr1 = __expf(m_i[0] - mn1);
            const float corr2 = __expf(m_i[1] - mn2);
            m_i[0] = mn1; m_i[1] = mn2;

            float rs1 = 0.0f, rs2 = 0.0f;
#pragma unroll
            for (int nf = 0; nf < 8; nf++) {
                float p0 = __expf(s[nf][0] - mn1);
                float p1 = __expf(s[nf][1] - mn1);
                float p2 = __expf(s[nf][2] - mn2);
                float p3 = __expf(s[nf][3] - mn2);
                rs1 += p0 + p1; rs2 += p2 + p3;
                s[nf][0] = p0; s[nf][1] = p1; s[nf][2] = p2; s[nf][3] = p3;
            }
            rs1 += __shfl_xor_sync(0xffffffffu, rs1, 1);
            rs1 += __shfl_xor_sync(0xffffffffu, rs1, 2);
            rs2 += __shfl_xor_sync(0xffffffffu, rs2, 1);
            rs2 += __shfl_xor_sync(0xffffffffu, rs2, 2);
            l_i[0] = l_i[0] * corr1 + rs1;
            l_i[1] = l_i[1] * corr2 + rs2;

#pragma unroll
            for (int d = 0; d < 16; d++) {
                o[d][0] *= corr1; o[d][1] *= corr1;
                o[d][2] *= corr2; o[d][3] *= corr2;
            }

            uint32_t pa[4][4];
#pragma unroll
            for (int tk = 0; tk < 4; tk++) {
                pa[tk][0] = packh2(s[2 * tk][0],     s[2 * tk][1]);
                pa[tk][1] = packh2(s[2 * tk][2],     s[2 * tk][3]);
                pa[tk][2] = packh2(s[2 * tk + 1][0], s[2 * tk + 1][1]);
                pa[tk][3] = packh2(s[2 * tk + 1][2], s[2 * tk + 1][3]);
            }

#pragma unroll
            for (int tk = 0; tk < 4; tk++) {
                const uint32_t rowo = (uint32_t)(16 * tk) * AQS * 2;
#pragma unroll
                for (int p = 0; p < 8; p++) {
                    uint32_t vh[4];
                    ldsm4t(vh, cVh + rowo + bV + (uint32_t)p * 32);
                    mma16(o[2 * p],     pa[tk], vh[0], vh[1]);
                    mma16(o[2 * p + 1], pa[tk], vh[2], vh[3]);
                }
            }
        }

        if (kb + 1 < nkb) {
            cp_wait<1>();      // next block's K/V landed
            __syncthreads();   // single barrier per iteration
        }
    }

    // ---- epilogue: fp16 output ----
    const float inv1 = 1.0f / l_i[0];
    const float inv2 = 1.0f / l_i[1];
#pragma unroll
    for (int d = 0; d < 16; d++) {
        const int cc = head * HD + d * 8 + 2 * (ln & 3);
        *(__half2*)(out + (size_t)r1g * HID + cc) =
            __floats2half2_rn(o[d][0] * inv1, o[d][1] * inv1);
        *(__half2*)(out + (size_t)r2g * HID + cc) =
            __floats2half2_rn(o[d][2] * inv2, o[d][3] * inv2);
    }
}

// ============================================================================
// Launch
// ============================================================================
extern "C" void kernel_launch(void* const* d_in, const int* in_sizes, int n_in,
                              void* d_out, int out_size) {
    const float* hidden = (const float*)d_in[0];
    const float* wpack  = (const float*)d_in[1];
    const float* wo     = (const float*)d_in[2];
    float* out = (float*)d_out;

    __half *qkvh, *h16, *wp16, *wo16, *at16;
    cudaGetSymbolAddress((void**)&qkvh, g_qkvh);
    cudaGetSymbolAddress((void**)&h16,  g_h16);
    cudaGetSymbolAddress((void**)&wp16, g_wp16);
    cudaGetSymbolAddress((void**)&wo16, g_wo16);
    cudaGetSymbolAddress((void**)&at16, g_attno16);

    cudaFuncSetAttribute((const void*)gemm16p<true>,
                         cudaFuncAttributeMaxDynamicSharedMemorySize, GEMM_SMEM);
    cudaFuncSetAttribute((const void*)gemm16p<false>,
                         cudaFuncAttributeMaxDynamicSharedMemorySize, GEMM_SMEM);
    cudaFuncSetAttribute((const void*)flash16_kernel,
                         cudaFuncAttributeMaxDynamicSharedMemorySize, FSMEM);

    // 0. pre-conversions: H, Wpack (full), Wo -> plain fp16
    cvt_fused3_kernel<<<8192, 256>>>(
        (const float4*)hidden, (uint2*)h16, (int)((size_t)S_LEN * HID / 4),
        (const float4*)wpack, (uint2*)wp16, (int)((size_t)QKV_N * HID / 4),
        (const float4*)wo, (uint2*)wo16, (int)((size_t)HID * HID / 4));

    // 1. QKV projection (plain fp16 B; fp16 output)
    dim3 g1(S_LEN / MT, QKV_N / NT);
    gemm16p<true><<<g1, 256, GEMM_SMEM>>>(
        h16, wp16, nullptr, qkvh, S_LEN, QKV_N, HID);

    // 2. Causal flash attention (BQ=128, plain fp16 QK) -> fp16
    dim3 g2(NH, S_LEN / BQ);
    flash16_kernel<<<g2, 256, FSMEM>>>(qkvh, at16);

    // 3. Output projection (plain fp16) -> fp32 out
    dim3 g3(S_LEN / MT, HID / NT);
    gemm16p<false><<<g3, 256, GEMM_SMEM>>>(
        at16, wo16, out, nullptr, S_LEN, HID, HID);
}